// round 2
// baseline (speedup 1.0000x reference)
#include <cuda_runtime.h>
#include <cuda_bf16.h>
#include <math.h>

// Problem constants
#define BS 2
#define NPTS 1024
#define H 8
#define DH 64
#define KNB 16
#define EMB 512
#define INNER 512
#define AINNER 256
#define POSH 64

// ---------------- scratch (static device globals; no allocation) ----------------
__device__ float g_qh[BS * H * NPTS * DH];          // (b,h,i,d)
__device__ float g_kh[BS * H * NPTS * DH];
__device__ float g_vh[BS * H * NPTS * DH];
__device__ int   g_nbr[BS * NPTS * KNB];
__device__ float g_rpe[BS * NPTS * KNB * INNER];    // (b,i,j,inner) 64 MB
__device__ float g_attn[BS * H * NPTS * KNB * DH];  // (b,h,i,j,d)   64 MB
__device__ float g_norm[BS * H * KNB * DH];
__device__ float g_agg[BS * NPTS * INNER];

// ---------------- GEMM: M=2048, N=512, K=512, tiled ----------------
// MODE 0: triple-projection (z selects input/weight/output), store permuted (b,h,i,d)
// MODE 1: C[row*512+col] = acc + bias[col] (output projection)
template <int MODE>
__global__ void gemm512_kernel(const float* __restrict__ A0,
                               const float* __restrict__ B0,
                               const float* __restrict__ A1,
                               const float* __restrict__ B1,
                               const float* __restrict__ A2,
                               const float* __restrict__ B2,
                               const float* __restrict__ bias,
                               float* __restrict__ C0,
                               float* __restrict__ C1,
                               float* __restrict__ C2) {
    const float* A = A0;
    const float* B = B0;
    float* C = C0;
    if (MODE == 0) {
        if (blockIdx.z == 1) { A = A1; B = B1; C = C1; }
        else if (blockIdx.z == 2) { A = A2; B = B2; C = C2; }
    }

    __shared__ float As[16][64];   // [k][m]
    __shared__ float Bs[16][64];   // [k][n]
    int t  = threadIdx.x;          // 256
    int m0 = blockIdx.y * 64;
    int n0 = blockIdx.x * 64;
    int tx = t & 15, ty = t >> 4;

    float acc[4][4];
#pragma unroll
    for (int u = 0; u < 4; u++)
#pragma unroll
        for (int v = 0; v < 4; v++) acc[u][v] = 0.f;

    int lm  = t >> 2;          // 0..63 A row within tile
    int lk4 = (t & 3) * 4;     // A k offset
    int lk  = t >> 4;          // 0..15 B row within tile
    int ln4 = (t & 15) * 4;    // B n offset

    for (int k0 = 0; k0 < 512; k0 += 16) {
        float4 av = *(const float4*)&A[(m0 + lm) * 512 + k0 + lk4];
        As[lk4 + 0][lm] = av.x;
        As[lk4 + 1][lm] = av.y;
        As[lk4 + 2][lm] = av.z;
        As[lk4 + 3][lm] = av.w;
        float4 bv = *(const float4*)&B[(k0 + lk) * 512 + n0 + ln4];
        *(float4*)&Bs[lk][ln4] = bv;
        __syncthreads();
#pragma unroll
        for (int k = 0; k < 16; k++) {
            float4 a4 = *(const float4*)&As[k][ty * 4];
            float4 b4 = *(const float4*)&Bs[k][tx * 4];
            float a[4] = {a4.x, a4.y, a4.z, a4.w};
            float b[4] = {b4.x, b4.y, b4.z, b4.w};
#pragma unroll
            for (int u = 0; u < 4; u++)
#pragma unroll
                for (int v = 0; v < 4; v++) acc[u][v] += a[u] * b[v];
        }
        __syncthreads();
    }

#pragma unroll
    for (int u = 0; u < 4; u++) {
#pragma unroll
        for (int v = 0; v < 4; v++) {
            int row = m0 + ty * 4 + u;
            int col = n0 + tx * 4 + v;
            if (MODE == 0) {
                int b = row >> 10, i = row & 1023;
                int hh = col >> 6, dd = col & 63;
                C[(((b * H + hh) * NPTS) + i) * DH + dd] = acc[u][v];
            } else {
                C[row * 512 + col] = acc[u][v] + bias[col];
            }
        }
    }
}

// ---------------- KNN: exact stable (d2, idx) ascending selection ----------------
__global__ void knn_kernel(const float* __restrict__ canonical) {
    __shared__ float sx[NPTS], sy[NPTS], sz[NPTS];
    int b = blockIdx.x >> 2;
    int t = threadIdx.x;  // 256
    for (int p = t; p < NPTS; p += 256) {
        sx[p] = canonical[(b * NPTS + p) * 3 + 0];
        sy[p] = canonical[(b * NPTS + p) * 3 + 1];
        sz[p] = canonical[(b * NPTS + p) * 3 + 2];
    }
    __syncthreads();
    int i = (blockIdx.x & 3) * 256 + t;
    float qx = sx[i], qy = sy[i], qz = sz[i];
    float prev_d = -1.f;
    int prev_j = -1;
    for (int s = 0; s < KNB; s++) {
        float bd = INFINITY;
        int bj = NPTS;
        for (int p = 0; p < NPTS; p++) {
            float dx = sx[p] - qx, dy = sy[p] - qy, dz = sz[p] - qz;
            float d2 = dx * dx + dy * dy + dz * dz;
            bool gt_prev = (d2 > prev_d) || (d2 == prev_d && p > prev_j);
            bool lt_best = (d2 < bd) || (d2 == bd && p < bj);
            if (gt_prev && lt_best) { bd = d2; bj = p; }
        }
        g_nbr[(b * NPTS + i) * KNB + s] = bj;
        prev_d = bd;
        prev_j = bj;
    }
}

// ---------------- RPE MLP: 3 -> 64 (relu) -> 512, per (b,i,j) ----------------
__global__ void rpe_kernel(const float* __restrict__ canonical,
                           const float* __restrict__ pw1, const float* __restrict__ pb1,
                           const float* __restrict__ pw2, const float* __restrict__ pb2) {
    int bij = blockIdx.x;       // 32768 = (b*1024+i)*16+j
    int j = bij & 15;
    int bi = bij >> 4;
    int t = threadIdx.x;        // 128
    __shared__ float h1[64];
    __shared__ float rel[3];
    if (t == 0) {
        int b = bi >> 10;
        int nv = g_nbr[bi * KNB + j];
        rel[0] = canonical[(b * NPTS + nv) * 3 + 0] - canonical[bi * 3 + 0];
        rel[1] = canonical[(b * NPTS + nv) * 3 + 1] - canonical[bi * 3 + 1];
        rel[2] = canonical[(b * NPTS + nv) * 3 + 2] - canonical[bi * 3 + 2];
    }
    __syncthreads();
    if (t < 64) {
        float a = rel[0] * pw1[t] + rel[1] * pw1[64 + t] + rel[2] * pw1[128 + t] + pb1[t];
        h1[t] = fmaxf(a, 0.f);
    }
    __syncthreads();
    float* outp = &g_rpe[(size_t)bij * INNER];
    for (int c = t; c < INNER; c += 128) {
        float acc = pb2[c];
#pragma unroll
        for (int e = 0; e < 64; e++) acc += h1[e] * pw2[e * INNER + c];
        outp[c] = acc;
    }
}

// faithful replication of the reference's flattened-view gather:
// returns base offset (in floats) of source row in (b,h,i,d) tensors
__device__ __forceinline__ int gather_row(int b, int h, int i, int j) {
    int m = 2 * i + (j >> 3);
    int ip = h * 128 + (m >> 4);
    int jp = m & 15;
    int nv = g_nbr[(b * NPTS + ip) * KNB + jp];
    int cc = nv * 8 + (j & 7);
    int h2 = cc >> 10;
    int i2 = cc & 1023;
    return ((b * H + h2) * NPTS + i2) * DH;
}

// ---------------- attn MLP (64->256 relu ->64) + softmax over j ----------------
__global__ void __launch_bounds__(256, 2)
attn_kernel(const float* __restrict__ aw1, const float* __restrict__ ab1,
            const float* __restrict__ aw2, const float* __restrict__ ab2) {
    int bhi = blockIdx.x;          // 16384
    int i = bhi & 1023;
    int h = (bhi >> 10) & 7;
    int b = bhi >> 13;
    int t = threadIdx.x;           // 256

    __shared__ float sx[KNB][DH];
    __shared__ float shdn[KNB][AINNER];
    __shared__ float ssim[KNB][DH];
    __shared__ int srow[KNB];

    if (t < KNB) srow[t] = gather_row(b, h, i, t);
    __syncthreads();

    // Phase A: x[j][d] = qg - kg + rpe
    {
        int j = t >> 4;
        int d = (t & 15) * 4;
        float4 qv = *(const float4*)&g_qh[srow[j] + d];
        float4 kv = *(const float4*)&g_kh[srow[j] + d];
        float4 rv = *(const float4*)&g_rpe[(size_t)((b * NPTS + i) * KNB + j) * INNER + h * DH + d];
        sx[j][d + 0] = qv.x - kv.x + rv.x;
        sx[j][d + 1] = qv.y - kv.y + rv.y;
        sx[j][d + 2] = qv.z - kv.z + rv.z;
        sx[j][d + 3] = qv.w - kv.w + rv.w;
    }
    __syncthreads();

    // Phase B: hidden e = relu(x . aw1[h,e,:] + ab1[h,e]); weights in regs, reused over j
    {
        int e = t;
        const float* w = &aw1[(h * AINNER + e) * DH];
        float wreg[DH];
#pragma unroll
        for (int d4 = 0; d4 < DH; d4 += 4) {
            float4 v = *(const float4*)&w[d4];
            wreg[d4 + 0] = v.x; wreg[d4 + 1] = v.y; wreg[d4 + 2] = v.z; wreg[d4 + 3] = v.w;
        }
        float bias = ab1[h * AINNER + e];
        for (int j = 0; j < KNB; j++) {
            float acc = bias;
#pragma unroll
            for (int d = 0; d < DH; d++) acc += wreg[d] * sx[j][d];
            shdn[j][e] = fmaxf(acc, 0.f);
        }
    }
    __syncthreads();

    // Phase C: sim[j][d] = hdn . aw2[h,d,:] + ab2[h,d]; thread owns (d, j-quartet)
    {
        int d = t & 63;
        int q4 = t >> 6;
        const float* w2 = &aw2[(h * DH + d) * AINNER];
        float acc[4];
        float bias = ab2[h * DH + d];
#pragma unroll
        for (int jj = 0; jj < 4; jj++) acc[jj] = bias;
        for (int e0 = 0; e0 < AINNER; e0 += 8) {
            float4 wa = *(const float4*)&w2[e0];
            float4 wb = *(const float4*)&w2[e0 + 4];
            float w[8] = {wa.x, wa.y, wa.z, wa.w, wb.x, wb.y, wb.z, wb.w};
#pragma unroll
            for (int jj = 0; jj < 4; jj++) {
                int j = q4 * 4 + jj;
#pragma unroll
                for (int ee = 0; ee < 8; ee++) acc[jj] += w[ee] * shdn[j][e0 + ee];
            }
        }
#pragma unroll
        for (int jj = 0; jj < 4; jj++) ssim[q4 * 4 + jj][d] = acc[jj];
    }
    __syncthreads();

    // Phase D: softmax over j per d, store attn
    if (t < DH) {
        int d = t;
        float m = -INFINITY;
#pragma unroll
        for (int j = 0; j < KNB; j++) m = fmaxf(m, ssim[j][d]);
        float ev[KNB];
        float s = 0.f;
#pragma unroll
        for (int j = 0; j < KNB; j++) {
            ev[j] = expf(ssim[j][d] - m);
            s += ev[j];
        }
        float inv = 1.f / s;
        size_t base = (size_t)bhi * KNB * DH + d;
#pragma unroll
        for (int j = 0; j < KNB; j++) g_attn[base + j * DH] = ev[j] * inv;
    }
}

// ---------------- norm over i (axis=2): norm[b,h,j,d] = sqrt(sum_i attn^2) ----------------
__global__ void norm_kernel() {
    int bhj = blockIdx.x;   // 256 = (b*8+h)*16 + j
    int j = bhj & 15;
    int bh = bhj >> 4;
    int d = threadIdx.x;    // 64
    size_t base = (size_t)bh * NPTS * KNB * DH + j * DH + d;
    float s = 0.f;
#pragma unroll 4
    for (int i = 0; i < NPTS; i++) {
        float v = g_attn[base + (size_t)i * KNB * DH];
        s += v * v;
    }
    g_norm[bhj * DH + d] = sqrtf(s);
}

// ---------------- aggregate: agg[b,i,h*64+d] = sum_j (attn/norm) * (vg + rpe) ----------------
__global__ void agg_kernel() {
    int bhi = blockIdx.x;   // 16384
    int i = bhi & 1023;
    int h = (bhi >> 10) & 7;
    int b = bhi >> 13;
    int t = threadIdx.x;    // 64
    __shared__ int srow[KNB];
    if (t < KNB) srow[t] = gather_row(b, h, i, t);
    __syncthreads();

    int d = t;
    int bh = b * H + h;
    size_t abase = (size_t)bhi * KNB * DH + d;
    float acc = 0.f;
#pragma unroll
    for (int j = 0; j < KNB; j++) {
        float a = g_attn[abase + j * DH];
        float nm = g_norm[(bh * KNB + j) * DH + d];
        a /= fmaxf(nm, 1e-12f);
        float vg = g_vh[srow[j] + d] +
                   g_rpe[(size_t)((b * NPTS + i) * KNB + j) * INNER + h * DH + d];
        acc += a * vg;
    }
    g_agg[(b * NPTS + i) * INNER + h * DH + d] = acc;
}

// ---------------- launch ----------------
extern "C" void kernel_launch(void* const* d_in, const int* in_sizes, int n_in,
                              void* d_out, int out_size) {
    const float* query     = (const float*)d_in[0];
    const float* key_in    = (const float*)d_in[1];
    const float* value     = (const float*)d_in[2];
    const float* canonical = (const float*)d_in[3];
    const float* w_q       = (const float*)d_in[4];
    const float* w_k       = (const float*)d_in[5];
    const float* w_v       = (const float*)d_in[6];
    const float* w_out     = (const float*)d_in[7];
    const float* b_out     = (const float*)d_in[8];
    const float* pos_w1    = (const float*)d_in[9];
    const float* pos_b1    = (const float*)d_in[10];
    const float* pos_w2    = (const float*)d_in[11];
    const float* pos_b2    = (const float*)d_in[12];
    const float* aw1       = (const float*)d_in[13];
    const float* ab1       = (const float*)d_in[14];
    const float* aw2       = (const float*)d_in[15];
    const float* ab2       = (const float*)d_in[16];
    float* out = (float*)d_out;

    float* qh;  cudaGetSymbolAddress((void**)&qh,  g_qh);
    float* kh;  cudaGetSymbolAddress((void**)&kh,  g_kh);
    float* vh;  cudaGetSymbolAddress((void**)&vh,  g_vh);
    float* agg; cudaGetSymbolAddress((void**)&agg, g_agg);

    // projections: one launch, z = {q,k,v}, store permuted into (b,h,i,d)
    dim3 pgrid(512 / 64, 2048 / 64, 3);
    gemm512_kernel<0><<<pgrid, 256>>>(query, w_q, key_in, w_k, value, w_v,
                                      nullptr, qh, kh, vh);

    knn_kernel<<<8, 256>>>(canonical);
    rpe_kernel<<<BS * NPTS * KNB, 128>>>(canonical, pos_w1, pos_b1, pos_w2, pos_b2);
    attn_kernel<<<BS * H * NPTS, 256>>>(aw1, ab1, aw2, ab2);
    norm_kernel<<<BS * H * KNB, 64>>>();
    agg_kernel<<<BS * H * NPTS, 64>>>();

    dim3 ogrid(512 / 64, 2048 / 64, 1);
    gemm512_kernel<1><<<ogrid, 256>>>(agg, w_out, nullptr, nullptr, nullptr, nullptr,
                                      b_out, out, nullptr, nullptr);
}

// round 3
// speedup vs baseline: 2.5044x; 2.5044x over previous
#include <cuda_runtime.h>
#include <cuda_bf16.h>
#include <math.h>

// Problem constants
#define BS 2
#define NPTS 1024
#define H 8
#define DH 64
#define KNB 16
#define EMB 512
#define INNER 512
#define AINNER 256
#define POSH 64
#define IT 8   // i-values per attn block

// ---------------- scratch (static device globals; no allocation) ----------------
__device__ float g_qh[BS * H * NPTS * DH];          // (b,h,i,d)
__device__ float g_kh[BS * H * NPTS * DH];
__device__ float g_vh[BS * H * NPTS * DH];
__device__ int   g_nbr[BS * NPTS * KNB];
__device__ float g_rpe[BS * NPTS * KNB * INNER];    // (b,i,j,inner) 64 MB
__device__ float g_attn[BS * H * NPTS * KNB * DH];  // (b,h,i,j,d)   64 MB
__device__ float g_norm[BS * H * KNB * DH];
__device__ float g_agg[BS * NPTS * INNER];

// ---------------- GEMM: M=2048, N=512, K=512, tiled ----------------
template <int MODE>
__global__ void gemm512_kernel(const float* __restrict__ A0,
                               const float* __restrict__ B0,
                               const float* __restrict__ A1,
                               const float* __restrict__ B1,
                               const float* __restrict__ A2,
                               const float* __restrict__ B2,
                               const float* __restrict__ bias,
                               float* __restrict__ C0,
                               float* __restrict__ C1,
                               float* __restrict__ C2) {
    const float* A = A0;
    const float* B = B0;
    float* C = C0;
    if (MODE == 0) {
        if (blockIdx.z == 1) { A = A1; B = B1; C = C1; }
        else if (blockIdx.z == 2) { A = A2; B = B2; C = C2; }
    }

    __shared__ float As[16][64];   // [k][m]
    __shared__ float Bs[16][64];   // [k][n]
    int t  = threadIdx.x;          // 256
    int m0 = blockIdx.y * 64;
    int n0 = blockIdx.x * 64;
    int tx = t & 15, ty = t >> 4;

    float acc[4][4];
#pragma unroll
    for (int u = 0; u < 4; u++)
#pragma unroll
        for (int v = 0; v < 4; v++) acc[u][v] = 0.f;

    int lm  = t >> 2;
    int lk4 = (t & 3) * 4;
    int lk  = t >> 4;
    int ln4 = (t & 15) * 4;

    for (int k0 = 0; k0 < 512; k0 += 16) {
        float4 av = *(const float4*)&A[(m0 + lm) * 512 + k0 + lk4];
        As[lk4 + 0][lm] = av.x;
        As[lk4 + 1][lm] = av.y;
        As[lk4 + 2][lm] = av.z;
        As[lk4 + 3][lm] = av.w;
        float4 bv = *(const float4*)&B[(k0 + lk) * 512 + n0 + ln4];
        *(float4*)&Bs[lk][ln4] = bv;
        __syncthreads();
#pragma unroll
        for (int k = 0; k < 16; k++) {
            float4 a4 = *(const float4*)&As[k][ty * 4];
            float4 b4 = *(const float4*)&Bs[k][tx * 4];
            float a[4] = {a4.x, a4.y, a4.z, a4.w};
            float b[4] = {b4.x, b4.y, b4.z, b4.w};
#pragma unroll
            for (int u = 0; u < 4; u++)
#pragma unroll
                for (int v = 0; v < 4; v++) acc[u][v] += a[u] * b[v];
        }
        __syncthreads();
    }

#pragma unroll
    for (int u = 0; u < 4; u++) {
#pragma unroll
        for (int v = 0; v < 4; v++) {
            int row = m0 + ty * 4 + u;
            int col = n0 + tx * 4 + v;
            if (MODE == 0) {
                int b = row >> 10, i = row & 1023;
                int hh = col >> 6, dd = col & 63;
                C[(((b * H + hh) * NPTS) + i) * DH + dd] = acc[u][v];
            } else {
                C[row * 512 + col] = acc[u][v] + bias[col];
            }
        }
    }
}

// ---------------- KNN: warp-per-query, exact stable (d2, idx) selection ----------------
__global__ void knn_kernel(const float* __restrict__ canonical) {
    __shared__ float sx[NPTS], sy[NPTS], sz[NPTS];
    int b = blockIdx.x >> 7;          // 128 blocks per batch
    int t = threadIdx.x;              // 256
    int wid = t >> 5, lane = t & 31;
    for (int p = t; p < NPTS; p += 256) {
        sx[p] = canonical[(b * NPTS + p) * 3 + 0];
        sy[p] = canonical[(b * NPTS + p) * 3 + 1];
        sz[p] = canonical[(b * NPTS + p) * 3 + 2];
    }
    __syncthreads();
    int i = (blockIdx.x & 127) * 8 + wid;
    float qx = sx[i], qy = sy[i], qz = sz[i];
    float prev_d = -1.f;
    int prev_j = -1;
    for (int s = 0; s < KNB; s++) {
        float bd = INFINITY;
        int bj = 1 << 30;
        for (int p = lane; p < NPTS; p += 32) {
            float dx = sx[p] - qx, dy = sy[p] - qy, dz = sz[p] - qz;
            float d2 = dx * dx + dy * dy + dz * dz;
            bool gt_prev = (d2 > prev_d) || (d2 == prev_d && p > prev_j);
            bool lt_best = (d2 < bd) || (d2 == bd && p < bj);
            if (gt_prev && lt_best) { bd = d2; bj = p; }
        }
#pragma unroll
        for (int off = 16; off; off >>= 1) {
            float od = __shfl_down_sync(0xFFFFFFFFu, bd, off);
            int   oj = __shfl_down_sync(0xFFFFFFFFu, bj, off);
            if (od < bd || (od == bd && oj < bj)) { bd = od; bj = oj; }
        }
        bd = __shfl_sync(0xFFFFFFFFu, bd, 0);
        bj = __shfl_sync(0xFFFFFFFFu, bj, 0);
        if (lane == 0) g_nbr[(b * NPTS + i) * KNB + s] = bj;
        prev_d = bd;
        prev_j = bj;
    }
}

// ---------------- RPE MLP: 3 -> 64 (relu) -> 512, one block per (b,i), all 16 j ----------------
__global__ void __launch_bounds__(256)
rpe_kernel(const float* __restrict__ canonical,
           const float* __restrict__ pw1, const float* __restrict__ pb1,
           const float* __restrict__ pw2, const float* __restrict__ pb2) {
    int bi = blockIdx.x;        // 2048
    int b = bi >> 10;
    int t = threadIdx.x;        // 256
    __shared__ float h1s[KNB][64];
    __shared__ float relS[KNB][3];

    if (t < KNB) {
        int nv = g_nbr[bi * KNB + t];
#pragma unroll
        for (int c = 0; c < 3; c++)
            relS[t][c] = canonical[(b * NPTS + nv) * 3 + c] - canonical[bi * 3 + c];
    }
    __syncthreads();
    {
        int e = t & 63;
        int j0 = (t >> 6) * 4;
        float w0 = pw1[e], w1 = pw1[64 + e], w2 = pw1[128 + e], bb = pb1[e];
#pragma unroll
        for (int jj = 0; jj < 4; jj++) {
            int j = j0 + jj;
            float a = relS[j][0] * w0 + relS[j][1] * w1 + relS[j][2] * w2 + bb;
            h1s[j][e] = fmaxf(a, 0.f);
        }
    }
    __syncthreads();

    int c4 = t & 127;           // output quartet index
    int jh = t >> 7;            // which 8 j's
    float4 bias = *(const float4*)&pb2[c4 * 4];
    float4 acc[8];
#pragma unroll
    for (int jj = 0; jj < 8; jj++) acc[jj] = bias;
    for (int e = 0; e < 64; e++) {
        float4 w = *(const float4*)&pw2[e * 512 + c4 * 4];
#pragma unroll
        for (int jj = 0; jj < 8; jj++) {
            float hv = h1s[jh * 8 + jj][e];
            acc[jj].x = fmaf(hv, w.x, acc[jj].x);
            acc[jj].y = fmaf(hv, w.y, acc[jj].y);
            acc[jj].z = fmaf(hv, w.z, acc[jj].z);
            acc[jj].w = fmaf(hv, w.w, acc[jj].w);
        }
    }
#pragma unroll
    for (int jj = 0; jj < 8; jj++)
        *(float4*)&g_rpe[((size_t)bi * KNB + jh * 8 + jj) * INNER + c4 * 4] = acc[jj];
}

// faithful replication of the reference's flattened-view gather
__device__ __forceinline__ int gather_row(int b, int h, int i, int j) {
    int m = 2 * i + (j >> 3);
    int ip = h * 128 + (m >> 4);
    int jp = m & 15;
    int nv = g_nbr[(b * NPTS + ip) * KNB + jp];
    int cc = nv * 8 + (j & 7);
    int h2 = cc >> 10;
    int i2 = cc & 1023;
    return ((b * H + h2) * NPTS + i2) * DH;
}

// ---------------- attn MLP (64->256 relu ->64) + softmax over j ----------------
// 256 threads, IT i's per block, both weight matrices persistent in registers.
__global__ void __launch_bounds__(256, 1)
attn_kernel(const float* __restrict__ aw1, const float* __restrict__ ab1,
            const float* __restrict__ aw2, const float* __restrict__ ab2) {
    int bhi0 = blockIdx.x * IT;    // grid = 16384/IT
    int i0 = bhi0 & 1023;
    int h = (bhi0 >> 10) & 7;
    int b = bhi0 >> 13;
    int t = threadIdx.x;           // 256

    __shared__ float4 sx4[KNB][16];       // x[j][d/4]
    __shared__ float4 shdn4[KNB][64];     // hidden[j][e/4]
    __shared__ float  red[4][KNB][DH];    // phase-C partials
    __shared__ int    srow[IT][KNB];
    __shared__ float  sab2[DH];

    // persistent weights
    int e = t;                             // phase-B output unit
    float w1reg[64];
    {
        const float* w = &aw1[(h * AINNER + e) * DH];
#pragma unroll
        for (int d4 = 0; d4 < 16; d4++) {
            float4 v = *(const float4*)&w[d4 * 4];
            w1reg[d4 * 4 + 0] = v.x; w1reg[d4 * 4 + 1] = v.y;
            w1reg[d4 * 4 + 2] = v.z; w1reg[d4 * 4 + 3] = v.w;
        }
    }
    float b1 = ab1[h * AINNER + e];

    int cd = t & 63, eq = t >> 6;          // phase-C mapping
    float4 w2reg[16];
    {
        const float* w2 = &aw2[(h * DH + cd) * AINNER + eq * 64];
#pragma unroll
        for (int k = 0; k < 16; k++) w2reg[k] = *(const float4*)&w2[k * 4];
    }
    if (t < DH) sab2[t] = ab2[h * DH + t];

    if (t < IT * KNB) {
        int ii = t >> 4, j = t & 15;
        srow[ii][j] = gather_row(b, h, i0 + ii, j);
    }
    __syncthreads();

    for (int ii = 0; ii < IT; ii++) {
        int i = i0 + ii;
        int bhi = bhi0 + ii;

        // Phase A: x[j][d] = qg - kg + rpe
        {
            int j = t >> 4, d4 = t & 15;
            int ro = srow[ii][j] + d4 * 4;
            float4 qv = *(const float4*)&g_qh[ro];
            float4 kv = *(const float4*)&g_kh[ro];
            float4 rv = *(const float4*)&g_rpe[((size_t)(b * NPTS + i) * KNB + j) * INNER + h * DH + d4 * 4];
            sx4[j][d4] = make_float4(qv.x - kv.x + rv.x, qv.y - kv.y + rv.y,
                                     qv.z - kv.z + rv.z, qv.w - kv.w + rv.w);
        }
        __syncthreads();

        // Phase B: hidden[j][e] = relu(x[j] . w1 + b1)
        {
#pragma unroll
            for (int j = 0; j < KNB; j++) {
                float s0 = 0.f, s1 = 0.f, s2 = 0.f, s3 = 0.f;
#pragma unroll
                for (int d4 = 0; d4 < 16; d4++) {
                    float4 xv = sx4[j][d4];
                    s0 = fmaf(w1reg[d4 * 4 + 0], xv.x, s0);
                    s1 = fmaf(w1reg[d4 * 4 + 1], xv.y, s1);
                    s2 = fmaf(w1reg[d4 * 4 + 2], xv.z, s2);
                    s3 = fmaf(w1reg[d4 * 4 + 3], xv.w, s3);
                }
                ((float*)&shdn4[j][0])[e] = fmaxf((s0 + s1) + (s2 + s3) + b1, 0.f);
            }
        }
        __syncthreads();

        // Phase C: partial sim over e-quarter eq for output dim cd
        {
            float acc[KNB];
#pragma unroll
            for (int j = 0; j < KNB; j++) acc[j] = 0.f;
#pragma unroll
            for (int k = 0; k < 16; k++) {
                float4 wv = w2reg[k];
#pragma unroll
                for (int j = 0; j < KNB; j++) {
                    float4 hv = shdn4[j][eq * 16 + k];
                    acc[j] = fmaf(wv.x, hv.x,
                             fmaf(wv.y, hv.y,
                             fmaf(wv.z, hv.z,
                             fmaf(wv.w, hv.w, acc[j]))));
                }
            }
#pragma unroll
            for (int j = 0; j < KNB; j++) red[eq][j][cd] = acc[j];
        }
        __syncthreads();

        // Phase D: reduce + softmax over j + store (t<64), overlaps next i's phase A
        if (t < DH) {
            int d = t;
            float sim[KNB];
            float m = -INFINITY;
#pragma unroll
            for (int j = 0; j < KNB; j++) {
                float s = red[0][j][d] + red[1][j][d] + red[2][j][d] + red[3][j][d] + sab2[d];
                sim[j] = s;
                m = fmaxf(m, s);
            }
            float sum = 0.f, ev[KNB];
#pragma unroll
            for (int j = 0; j < KNB; j++) { ev[j] = expf(sim[j] - m); sum += ev[j]; }
            float inv = 1.f / sum;
            size_t base = (size_t)bhi * KNB * DH + d;
#pragma unroll
            for (int j = 0; j < KNB; j++) g_attn[base + j * DH] = ev[j] * inv;
        }
        // red is only rewritten after two more __syncthreads (A,B of next i) -> safe
    }
}

// ---------------- norm over i: norm[b,h,j,d] = sqrt(sum_i attn^2) ----------------
__global__ void norm_kernel() {
    int bhj = blockIdx.x;   // 256
    int j = bhj & 15;
    int bh = bhj >> 4;
    int t = threadIdx.x;    // 256
    int d = t & 63, iq = t >> 6;
    size_t base = (size_t)bh * NPTS * KNB * DH + j * DH + d;
    float s = 0.f;
#pragma unroll 4
    for (int i = iq * 256; i < iq * 256 + 256; i++) {
        float v = g_attn[base + (size_t)i * KNB * DH];
        s += v * v;
    }
    __shared__ float r[4][64];
    r[iq][d] = s;
    __syncthreads();
    if (t < 64) g_norm[bhj * DH + t] = sqrtf(r[0][t] + r[1][t] + r[2][t] + r[3][t]);
}

// ---------------- aggregate: agg[b,i,h*64+d] = sum_j (attn/norm) * (vg + rpe) ----------------
__global__ void agg_kernel() {
    int t = threadIdx.x;       // 256 -> 4 i's per block
    int ii = t >> 6;
    int d = t & 63;
    int bhi = blockIdx.x * 4 + ii;
    int i = bhi & 1023;
    int h = (bhi >> 10) & 7;
    int b = bhi >> 13;

    __shared__ int srow[4][KNB];
    if (t < 64) {
        int i2 = t >> 4, j = t & 15;
        srow[i2][j] = gather_row(b, h, (blockIdx.x * 4 + i2) & 1023, j);
    }
    __syncthreads();

    int bh = b * H + h;
    size_t abase = (size_t)bhi * KNB * DH + d;
    float acc = 0.f;
#pragma unroll
    for (int j = 0; j < KNB; j++) {
        float a = g_attn[abase + j * DH];
        float nm = g_norm[(bh * KNB + j) * DH + d];
        a /= fmaxf(nm, 1e-12f);
        float vg = g_vh[srow[ii][j] + d] +
                   g_rpe[(size_t)((b * NPTS + i) * KNB + j) * INNER + h * DH + d];
        acc = fmaf(a, vg, acc);
    }
    g_agg[(b * NPTS + i) * INNER + h * DH + d] = acc;
}

// ---------------- launch ----------------
extern "C" void kernel_launch(void* const* d_in, const int* in_sizes, int n_in,
                              void* d_out, int out_size) {
    const float* query     = (const float*)d_in[0];
    const float* key_in    = (const float*)d_in[1];
    const float* value     = (const float*)d_in[2];
    const float* canonical = (const float*)d_in[3];
    const float* w_q       = (const float*)d_in[4];
    const float* w_k       = (const float*)d_in[5];
    const float* w_v       = (const float*)d_in[6];
    const float* w_out     = (const float*)d_in[7];
    const float* b_out     = (const float*)d_in[8];
    const float* pos_w1    = (const float*)d_in[9];
    const float* pos_b1    = (const float*)d_in[10];
    const float* pos_w2    = (const float*)d_in[11];
    const float* pos_b2    = (const float*)d_in[12];
    const float* aw1       = (const float*)d_in[13];
    const float* ab1       = (const float*)d_in[14];
    const float* aw2       = (const float*)d_in[15];
    const float* ab2       = (const float*)d_in[16];
    float* out = (float*)d_out;

    float* qh;  cudaGetSymbolAddress((void**)&qh,  g_qh);
    float* kh;  cudaGetSymbolAddress((void**)&kh,  g_kh);
    float* vh;  cudaGetSymbolAddress((void**)&vh,  g_vh);
    float* agg; cudaGetSymbolAddress((void**)&agg, g_agg);

    dim3 pgrid(512 / 64, 2048 / 64, 3);
    gemm512_kernel<0><<<pgrid, 256>>>(query, w_q, key_in, w_k, value, w_v,
                                      nullptr, qh, kh, vh);

    knn_kernel<<<256, 256>>>(canonical);
    rpe_kernel<<<BS * NPTS, 256>>>(canonical, pos_w1, pos_b1, pos_w2, pos_b2);
    attn_kernel<<<BS * H * NPTS / IT, 256>>>(aw1, ab1, aw2, ab2);
    norm_kernel<<<BS * H * KNB, 256>>>();
    agg_kernel<<<BS * H * NPTS / 4, 256>>>();

    dim3 ogrid(512 / 64, 2048 / 64, 1);
    gemm512_kernel<1><<<ogrid, 256>>>(agg, w_out, nullptr, nullptr, nullptr, nullptr,
                                      b_out, out, nullptr, nullptr);
}

// round 6
// speedup vs baseline: 4.7249x; 1.8867x over previous
#include <cuda_runtime.h>
#include <cuda_bf16.h>
#include <cstdint>
#include <cstring>
#include <math.h>

// Problem constants
#define BS 2
#define NPTS 1024
#define H 8
#define DH 64
#define KNB 16
#define EMB 512
#define INNER 512
#define AINNER 256
#define POSH 64

// ---------------- scratch (static device globals; no allocation) ----------------
__device__ float g_qh[BS * H * NPTS * DH];
__device__ float g_kh[BS * H * NPTS * DH];
__device__ float g_vh[BS * H * NPTS * DH];
__device__ int   g_nbr[BS * NPTS * KNB];
__device__ float g_rpe[BS * NPTS * KNB * INNER];
__device__ float g_attn[BS * H * NPTS * KNB * DH];
__device__ float g_norm[BS * H * KNB * DH];
__device__ float g_agg[BS * NPTS * INNER];

// ---------------- GEMM: M=2048, N=512, K=512, tiled ----------------
template <int MODE>
__global__ void gemm512_kernel(const float* __restrict__ A0,
                               const float* __restrict__ B0,
                               const float* __restrict__ A1,
                               const float* __restrict__ B1,
                               const float* __restrict__ A2,
                               const float* __restrict__ B2,
                               const float* __restrict__ bias,
                               float* __restrict__ C0,
                               float* __restrict__ C1,
                               float* __restrict__ C2) {
    const float* A = A0;
    const float* B = B0;
    float* C = C0;
    if (MODE == 0) {
        if (blockIdx.z == 1) { A = A1; B = B1; C = C1; }
        else if (blockIdx.z == 2) { A = A2; B = B2; C = C2; }
    }

    __shared__ float As[16][64];
    __shared__ float Bs[16][64];
    int t  = threadIdx.x;
    int m0 = blockIdx.y * 64;
    int n0 = blockIdx.x * 64;
    int tx = t & 15, ty = t >> 4;

    float acc[4][4];
#pragma unroll
    for (int u = 0; u < 4; u++) {
#pragma unroll
        for (int v = 0; v < 4; v++) acc[u][v] = 0.f;
    }

    int lm  = t >> 2;
    int lk4 = (t & 3) * 4;
    int lk  = t >> 4;
    int ln4 = (t & 15) * 4;

    for (int k0 = 0; k0 < 512; k0 += 16) {
        float4 av = *(const float4*)&A[(m0 + lm) * 512 + k0 + lk4];
        As[lk4 + 0][lm] = av.x;
        As[lk4 + 1][lm] = av.y;
        As[lk4 + 2][lm] = av.z;
        As[lk4 + 3][lm] = av.w;
        float4 bv = *(const float4*)&B[(k0 + lk) * 512 + n0 + ln4];
        *(float4*)&Bs[lk][ln4] = bv;
        __syncthreads();
#pragma unroll
        for (int k = 0; k < 16; k++) {
            float4 a4 = *(const float4*)&As[k][ty * 4];
            float4 b4 = *(const float4*)&Bs[k][tx * 4];
            float a[4] = {a4.x, a4.y, a4.z, a4.w};
            float b[4] = {b4.x, b4.y, b4.z, b4.w};
#pragma unroll
            for (int u = 0; u < 4; u++) {
#pragma unroll
                for (int v = 0; v < 4; v++) acc[u][v] += a[u] * b[v];
            }
        }
        __syncthreads();
    }

#pragma unroll
    for (int u = 0; u < 4; u++) {
#pragma unroll
        for (int v = 0; v < 4; v++) {
            int row = m0 + ty * 4 + u;
            int col = n0 + tx * 4 + v;
            if (MODE == 0) {
                int b = row >> 10, i = row & 1023;
                int hh = col >> 6, dd = col & 63;
                C[(((b * H + hh) * NPTS) + i) * DH + dd] = acc[u][v];
            } else {
                C[row * 512 + col] = acc[u][v] + bias[col];
            }
        }
    }
}

// ---------------- KNN: warp-per-query, exact stable (d2, idx) selection ----------------
__global__ void knn_kernel(const float* __restrict__ canonical) {
    __shared__ float sx[NPTS], sy[NPTS], sz[NPTS];
    int b = blockIdx.x >> 7;
    int t = threadIdx.x;
    int wid = t >> 5, lane = t & 31;
    for (int p = t; p < NPTS; p += 256) {
        sx[p] = canonical[(b * NPTS + p) * 3 + 0];
        sy[p] = canonical[(b * NPTS + p) * 3 + 1];
        sz[p] = canonical[(b * NPTS + p) * 3 + 2];
    }
    __syncthreads();
    int i = (blockIdx.x & 127) * 8 + wid;
    float qx = sx[i], qy = sy[i], qz = sz[i];
    float prev_d = -1.f;
    int prev_j = -1;
    for (int s = 0; s < KNB; s++) {
        float bd = INFINITY;
        int bj = 1 << 30;
        for (int p = lane; p < NPTS; p += 32) {
            float dx = sx[p] - qx, dy = sy[p] - qy, dz = sz[p] - qz;
            float d2 = dx * dx + dy * dy + dz * dz;
            bool gt_prev = (d2 > prev_d) || (d2 == prev_d && p > prev_j);
            bool lt_best = (d2 < bd) || (d2 == bd && p < bj);
            if (gt_prev && lt_best) { bd = d2; bj = p; }
        }
#pragma unroll
        for (int off = 16; off; off >>= 1) {
            float od = __shfl_down_sync(0xFFFFFFFFu, bd, off);
            int   oj = __shfl_down_sync(0xFFFFFFFFu, bj, off);
            if (od < bd || (od == bd && oj < bj)) { bd = od; bj = oj; }
        }
        bd = __shfl_sync(0xFFFFFFFFu, bd, 0);
        bj = __shfl_sync(0xFFFFFFFFu, bj, 0);
        if (lane == 0) g_nbr[(b * NPTS + i) * KNB + s] = bj;
        prev_d = bd;
        prev_j = bj;
    }
}

// ---------------- RPE MLP: 3 -> 64 (relu) -> 512 ----------------
__global__ void __launch_bounds__(256)
rpe_kernel(const float* __restrict__ canonical,
           const float* __restrict__ pw1, const float* __restrict__ pb1,
           const float* __restrict__ pw2, const float* __restrict__ pb2) {
    int bi = blockIdx.x;
    int b = bi >> 10;
    int t = threadIdx.x;
    __shared__ float h1s[KNB][64];
    __shared__ float relS[KNB][3];

    if (t < KNB) {
        int nv = g_nbr[bi * KNB + t];
#pragma unroll
        for (int c = 0; c < 3; c++) {
            relS[t][c] = canonical[(b * NPTS + nv) * 3 + c] - canonical[bi * 3 + c];
        }
    }
    __syncthreads();

    int e = t & 63;
    int j0 = (t >> 6) * 4;
    float w0 = pw1[e], w1 = pw1[64 + e], w2 = pw1[128 + e], bb = pb1[e];
#pragma unroll
    for (int jj = 0; jj < 4; jj++) {
        int j = j0 + jj;
        float a = relS[j][0] * w0 + relS[j][1] * w1 + relS[j][2] * w2 + bb;
        h1s[j][e] = fmaxf(a, 0.f);
    }
    __syncthreads();

    int c4 = t & 127;
    int jh = t >> 7;
    float4 bias = *(const float4*)&pb2[c4 * 4];
    float4 acc[8];
#pragma unroll
    for (int jj = 0; jj < 8; jj++) acc[jj] = bias;
    for (int ee = 0; ee < 64; ee++) {
        float4 w = *(const float4*)&pw2[ee * 512 + c4 * 4];
#pragma unroll
        for (int jj = 0; jj < 8; jj++) {
            float hv = h1s[jh * 8 + jj][ee];
            acc[jj].x = fmaf(hv, w.x, acc[jj].x);
            acc[jj].y = fmaf(hv, w.y, acc[jj].y);
            acc[jj].z = fmaf(hv, w.z, acc[jj].z);
            acc[jj].w = fmaf(hv, w.w, acc[jj].w);
        }
    }
#pragma unroll
    for (int jj = 0; jj < 8; jj++) {
        *(float4*)&g_rpe[((size_t)bi * KNB + jh * 8 + jj) * INNER + c4 * 4] = acc[jj];
    }
}

// faithful replication of the reference's flattened-view gather
__device__ __forceinline__ int gather_row(int b, int h, int i, int j) {
    int m = 2 * i + (j >> 3);
    int ip = h * 128 + (m >> 4);
    int jp = m & 15;
    int nv = g_nbr[(b * NPTS + ip) * KNB + jp];
    int cc = nv * 8 + (j & 7);
    int h2 = cc >> 10;
    int i2 = cc & 1023;
    return ((b * H + h2) * NPTS + i2) * DH;
}

// ---------------- tensor-core attn helpers ----------------
__device__ __forceinline__ uint32_t smem_u32(const void* p) {
    uint32_t a;
    asm("{ .reg .u64 tmp; cvta.to.shared.u64 tmp, %1; cvt.u32.u64 %0, tmp; }"
        : "=r"(a) : "l"(p));
    return a;
}

__device__ __forceinline__ void ldsm4p(uint32_t* r, uint32_t addr) {
    asm volatile("ldmatrix.sync.aligned.m8n8.x4.shared.b16 {%0,%1,%2,%3}, [%4];"
                 : "=r"(r[0]), "=r"(r[1]), "=r"(r[2]), "=r"(r[3])
                 : "r"(addr));
}

__device__ __forceinline__ void mmabf(float* c, const uint32_t* a, uint32_t b0, uint32_t b1) {
    asm volatile("mma.sync.aligned.m16n8k16.row.col.f32.bf16.bf16.f32 "
                 "{%0,%1,%2,%3}, {%4,%5,%6,%7}, {%8,%9}, {%0,%1,%2,%3};"
                 : "+f"(c[0]), "+f"(c[1]), "+f"(c[2]), "+f"(c[3])
                 : "r"(a[0]), "r"(a[1]), "r"(a[2]), "r"(a[3]), "r"(b0), "r"(b1));
}

// split two floats into packed bf16 hi pair + lo (residual) pair
__device__ __forceinline__ void split_pair(float v0, float v1, uint32_t* hi, uint32_t* lo) {
    __nv_bfloat162 hv = __floats2bfloat162_rn(v0, v1);
    float f0 = __low2float(hv);
    float f1 = __high2float(hv);
    __nv_bfloat162 lv = __floats2bfloat162_rn(v0 - f0, v1 - f1);
    uint32_t uh, ul;
    memcpy(&uh, &hv, 4);
    memcpy(&ul, &lv, 4);
    *hi = uh;
    *lo = ul;
}

// smem layout (bytes)
#define AT_W1H 0
#define AT_W1L 36864
#define AT_W2H 73728
#define AT_W2L 107520
#define AT_X   141312
#define AT_AB1 178176
#define AT_AB2 179200
#define AT_SMEM 179456

// warp-per-i tensor-core attn MLP (bf16x3) + softmax. 32 i per block, h uniform.
__global__ void __launch_bounds__(256, 1)
attn_tc_kernel(const float* __restrict__ aw1, const float* __restrict__ ab1,
               const float* __restrict__ aw2, const float* __restrict__ ab2) {
    extern __shared__ char smem[];
    uint32_t sb = smem_u32(smem);
    int t = threadIdx.x;
    int w = t >> 5;
    int lane = t & 31;
    int h = ((blockIdx.x * 32) >> 10) & 7;

    __nv_bfloat16* W1H = (__nv_bfloat16*)(smem + AT_W1H);   // [256][72]
    __nv_bfloat16* W1L = (__nv_bfloat16*)(smem + AT_W1L);
    __nv_bfloat16* W2H = (__nv_bfloat16*)(smem + AT_W2H);   // [64][264]
    __nv_bfloat16* W2L = (__nv_bfloat16*)(smem + AT_W2L);
    float* sab1 = (float*)(smem + AT_AB1);
    float* sab2 = (float*)(smem + AT_AB2);

    // weight prep: fp32 -> bf16 hi/lo planes (once per block)
    for (int idx = t; idx < 256 * 64; idx += 256) {
        int e = idx >> 6;
        int d = idx & 63;
        float v = aw1[(h * AINNER + e) * DH + d];
        __nv_bfloat16 hi = __float2bfloat16_rn(v);
        W1H[e * 72 + d] = hi;
        W1L[e * 72 + d] = __float2bfloat16_rn(v - __bfloat162float(hi));
    }
    for (int idx = t; idx < 64 * 256; idx += 256) {
        int d = idx >> 8;
        int e = idx & 255;
        float v = aw2[(h * DH + d) * AINNER + e];
        __nv_bfloat16 hi = __float2bfloat16_rn(v);
        W2H[d * 264 + e] = hi;
        W2L[d * 264 + e] = __float2bfloat16_rn(v - __bfloat162float(hi));
    }
    sab1[t] = ab1[h * AINNER + t];
    if (t < 64) sab2[t] = ab2[h * DH + t];
    __syncthreads();

    int r  = lane >> 2;
    int cq = lane & 3;
    int rr = lane & 7;
    int g  = lane >> 3;
    uint32_t xh_base = sb + AT_X + w * 4608;
    uint32_t xl_base = xh_base + 2304;
    char* xh_ptr = smem + AT_X + w * 4608;
    char* xl_ptr = xh_ptr + 2304;
    uint32_t w1h_base = sb + AT_W1H;
    uint32_t w1l_base = sb + AT_W1L;
    uint32_t w2h_base = sb + AT_W2H;
    uint32_t w2l_base = sb + AT_W2L;

    for (int l = 0; l < 4; l++) {
        int bhi = blockIdx.x * 32 + w * 4 + l;
        int i = bhi & 1023;
        int b = bhi >> 13;

        int sr = 0;
        if (lane < 16) sr = gather_row(b, h, i, lane);

        // phase A: X = qg - kg + rpe, split into bf16 hi/lo planes (rows of 72 elems)
#pragma unroll
        for (int it = 0; it < 8; it++) {
            int idx = lane + it * 32;
            int j  = idx >> 4;
            int d4 = idx & 15;
            int ro = __shfl_sync(0xFFFFFFFFu, sr, j) + d4 * 4;
            float4 qv = *(const float4*)&g_qh[ro];
            float4 kv = *(const float4*)&g_kh[ro];
            float4 rv = *(const float4*)&g_rpe[((size_t)(b * NPTS + i) * KNB + j) * INNER + h * DH + d4 * 4];
            uint32_t h01, l01, h23, l23;
            split_pair(qv.x - kv.x + rv.x, qv.y - kv.y + rv.y, &h01, &l01);
            split_pair(qv.z - kv.z + rv.z, qv.w - kv.w + rv.w, &h23, &l23);
            int off = j * 144 + d4 * 8;
            *(uint32_t*)(xh_ptr + off)     = h01;
            *(uint32_t*)(xh_ptr + off + 4) = h23;
            *(uint32_t*)(xl_ptr + off)     = l01;
            *(uint32_t*)(xl_ptr + off + 4) = l23;
        }
        __syncwarp();

        // acc2: sim (8 n-tiles of m16n8 over d), init with ab2
        float acc2[8][4];
#pragma unroll
        for (int nt2 = 0; nt2 < 8; nt2++) {
            int d0 = nt2 * 8 + 2 * cq;
            acc2[nt2][0] = sab2[d0];
            acc2[nt2][1] = sab2[d0 + 1];
            acc2[nt2][2] = acc2[nt2][0];
            acc2[nt2][3] = acc2[nt2][1];
        }

#pragma unroll
        for (int half = 0; half < 2; half++) {
            // GEMM1: hdn[16][128] = X[16][64] @ W1(half)^T + ab1, bf16x3
            float acc1[16][4];
#pragma unroll
            for (int nt = 0; nt < 16; nt++) {
                int e0 = (half * 16 + nt) * 8 + 2 * cq;
                acc1[nt][0] = sab1[e0];
                acc1[nt][1] = sab1[e0 + 1];
                acc1[nt][2] = acc1[nt][0];
                acc1[nt][3] = acc1[nt][1];
            }
#pragma unroll
            for (int kt = 0; kt < 4; kt++) {
                uint32_t ahi[4];
                uint32_t alo[4];
                uint32_t aoff = (uint32_t)((rr + (g & 1) * 8) * 144 + (kt * 16 + (g >> 1) * 8) * 2);
                ldsm4p(ahi, xh_base + aoff);
                ldsm4p(alo, xl_base + aoff);
#pragma unroll
                for (int ntp = 0; ntp < 8; ntp++) {
                    int erow = (half * 16 + 2 * ntp + (g >> 1)) * 8 + rr;
                    int dcol = kt * 16 + (g & 1) * 8;
                    uint32_t boff = (uint32_t)(erow * 144 + dcol * 2);
                    uint32_t bhv[4];
                    uint32_t blv[4];
                    ldsm4p(bhv, w1h_base + boff);
                    ldsm4p(blv, w1l_base + boff);
                    mmabf(acc1[2 * ntp], ahi, bhv[0], bhv[1]);
                    mmabf(acc1[2 * ntp], ahi, blv[0], blv[1]);
                    mmabf(acc1[2 * ntp], alo, bhv[0], bhv[1]);
                    mmabf(acc1[2 * ntp + 1], ahi, bhv[2], bhv[3]);
                    mmabf(acc1[2 * ntp + 1], ahi, blv[2], blv[3]);
                    mmabf(acc1[2 * ntp + 1], alo, bhv[2], bhv[3]);
                }
            }
            // relu + register-direct conversion to GEMM2 A-fragments, then GEMM2
#pragma unroll
            for (int ap = 0; ap < 8; ap++) {
                float v0 = fmaxf(acc1[2 * ap][0], 0.f);
                float v1 = fmaxf(acc1[2 * ap][1], 0.f);
                float v2 = fmaxf(acc1[2 * ap][2], 0.f);
                float v3 = fmaxf(acc1[2 * ap][3], 0.f);
                float v4 = fmaxf(acc1[2 * ap + 1][0], 0.f);
                float v5 = fmaxf(acc1[2 * ap + 1][1], 0.f);
                float v6 = fmaxf(acc1[2 * ap + 1][2], 0.f);
                float v7 = fmaxf(acc1[2 * ap + 1][3], 0.f);
                uint32_t a2h[4];
                uint32_t a2l[4];
                split_pair(v0, v1, &a2h[0], &a2l[0]);
                split_pair(v2, v3, &a2h[1], &a2l[1]);
                split_pair(v4, v5, &a2h[2], &a2l[2]);
                split_pair(v6, v7, &a2h[3], &a2l[3]);
                int kcol = (half * 8 + ap) * 16;
#pragma unroll
                for (int np = 0; np < 4; np++) {
                    int drow = (2 * np + (g >> 1)) * 8 + rr;
                    int ecol = kcol + (g & 1) * 8;
                    uint32_t b2off = (uint32_t)(drow * 528 + ecol * 2);
                    uint32_t b2h[4];
                    uint32_t b2l[4];
                    ldsm4p(b2h, w2h_base + b2off);
                    ldsm4p(b2l, w2l_base + b2off);
                    mmabf(acc2[2 * np], a2h, b2h[0], b2h[1]);
                    mmabf(acc2[2 * np], a2h, b2l[0], b2l[1]);
                    mmabf(acc2[2 * np], a2l, b2h[0], b2h[1]);
                    mmabf(acc2[2 * np + 1], a2h, b2h[2], b2h[3]);
                    mmabf(acc2[2 * np + 1], a2h, b2l[2], b2l[3]);
                    mmabf(acc2[2 * np + 1], a2l, b2h[2], b2h[3]);
                }
            }
        }

        // softmax over j (accumulator rows) per d column, store attn
        size_t base = (size_t)bhi * KNB * DH;
#pragma unroll
        for (int nt2 = 0; nt2 < 8; nt2++) {
            float c0 = acc2[nt2][0];
            float c1 = acc2[nt2][1];
            float c2 = acc2[nt2][2];
            float c3 = acc2[nt2][3];
            float ma = fmaxf(c0, c2);
            float mb = fmaxf(c1, c3);
#pragma unroll
            for (int mk = 4; mk <= 16; mk <<= 1) {
                ma = fmaxf(ma, __shfl_xor_sync(0xFFFFFFFFu, ma, mk));
                mb = fmaxf(mb, __shfl_xor_sync(0xFFFFFFFFu, mb, mk));
            }
            float e0 = expf(c0 - ma);
            float e2 = expf(c2 - ma);
            float e1 = expf(c1 - mb);
            float e3 = expf(c3 - mb);
            float sa = e0 + e2;
            float sc = e1 + e3;
#pragma unroll
            for (int mk = 4; mk <= 16; mk <<= 1) {
                sa += __shfl_xor_sync(0xFFFFFFFFu, sa, mk);
                sc += __shfl_xor_sync(0xFFFFFFFFu, sc, mk);
            }
            float ia = 1.f / sa;
            float ic = 1.f / sc;
            int d0 = nt2 * 8 + 2 * cq;
            *(float2*)&g_attn[base + (size_t)r * DH + d0] = make_float2(e0 * ia, e1 * ic);
            *(float2*)&g_attn[base + (size_t)(r + 8) * DH + d0] = make_float2(e2 * ia, e3 * ic);
        }
        __syncwarp();
    }
}

// ---------------- norm over i: norm[b,h,j,d] = sqrt(sum_i attn^2) ----------------
__global__ void norm_kernel() {
    int bhj = blockIdx.x;
    int j = bhj & 15;
    int bh = bhj >> 4;
    int t = threadIdx.x;
    int d = t & 63;
    int iq = t >> 6;
    size_t base = (size_t)bh * NPTS * KNB * DH + j * DH + d;
    float s = 0.f;
#pragma unroll 4
    for (int i = iq * 256; i < iq * 256 + 256; i++) {
        float v = g_attn[base + (size_t)i * KNB * DH];
        s += v * v;
    }
    __shared__ float rshared[4][64];
    rshared[iq][d] = s;
    __syncthreads();
    if (t < 64) g_norm[bhj * DH + t] = sqrtf(rshared[0][t] + rshared[1][t] + rshared[2][t] + rshared[3][t]);
}

// ---------------- aggregate ----------------
__global__ void agg_kernel() {
    int t = threadIdx.x;
    int ii = t >> 6;
    int d = t & 63;
    int bhi = blockIdx.x * 4 + ii;
    int i = bhi & 1023;
    int h = (bhi >> 10) & 7;
    int b = bhi >> 13;

    __shared__ int srow[4][KNB];
    if (t < 64) {
        int i2 = t >> 4;
        int j = t & 15;
        srow[i2][j] = gather_row(b, h, (blockIdx.x * 4 + i2) & 1023, j);
    }
    __syncthreads();

    int bh = b * H + h;
    size_t abase = (size_t)bhi * KNB * DH + d;
    float acc = 0.f;
#pragma unroll
    for (int j = 0; j < KNB; j++) {
        float a = g_attn[abase + j * DH];
        float nm = g_norm[(bh * KNB + j) * DH + d];
        a /= fmaxf(nm, 1e-12f);
        float vg = g_vh[srow[ii][j] + d] +
                   g_rpe[(size_t)((b * NPTS + i) * KNB + j) * INNER + h * DH + d];
        acc = fmaf(a, vg, acc);
    }
    g_agg[(b * NPTS + i) * INNER + h * DH + d] = acc;
}

// ---------------- launch ----------------
extern "C" void kernel_launch(void* const* d_in, const int* in_sizes, int n_in,
                              void* d_out, int out_size) {
    const float* query     = (const float*)d_in[0];
    const float* key_in    = (const float*)d_in[1];
    const float* value     = (const float*)d_in[2];
    const float* canonical = (const float*)d_in[3];
    const float* w_q       = (const float*)d_in[4];
    const float* w_k       = (const float*)d_in[5];
    const float* w_v       = (const float*)d_in[6];
    const float* w_out     = (const float*)d_in[7];
    const float* b_out     = (const float*)d_in[8];
    const float* pos_w1    = (const float*)d_in[9];
    const float* pos_b1    = (const float*)d_in[10];
    const float* pos_w2    = (const float*)d_in[11];
    const float* pos_b2    = (const float*)d_in[12];
    const float* aw1       = (const float*)d_in[13];
    const float* ab1       = (const float*)d_in[14];
    const float* aw2       = (const float*)d_in[15];
    const float* ab2       = (const float*)d_in[16];
    float* out = (float*)d_out;

    float* qh;  cudaGetSymbolAddress((void**)&qh,  g_qh);
    float* kh;  cudaGetSymbolAddress((void**)&kh,  g_kh);
    float* vh;  cudaGetSymbolAddress((void**)&vh,  g_vh);
    float* agg; cudaGetSymbolAddress((void**)&agg, g_agg);

    cudaFuncSetAttribute(attn_tc_kernel,
                         cudaFuncAttributeMaxDynamicSharedMemorySize, AT_SMEM);

    dim3 pgrid(512 / 64, 2048 / 64, 3);
    gemm512_kernel<0><<<pgrid, 256>>>(query, w_q, key_in, w_k, value, w_v,
                                      nullptr, qh, kh, vh);

    knn_kernel<<<256, 256>>>(canonical);
    rpe_kernel<<<BS * NPTS, 256>>>(canonical, pos_w1, pos_b1, pos_w2, pos_b2);
    attn_tc_kernel<<<BS * H * NPTS / 32, 256, AT_SMEM>>>(aw1, ab1, aw2, ab2);
    norm_kernel<<<BS * H * KNB, 256>>>();
    agg_kernel<<<BS * H * NPTS / 4, 256>>>();

    dim3 ogrid(512 / 64, 2048 / 64, 1);
    gemm512_kernel<1><<<ogrid, 256>>>(agg, w_out, nullptr, nullptr, nullptr, nullptr,
                                      b_out, out, nullptr, nullptr);
}

// round 7
// speedup vs baseline: 5.7619x; 1.2195x over previous
#include <cuda_runtime.h>
#include <cuda_bf16.h>
#include <cstdint>
#include <cstring>
#include <math.h>

// Problem constants
#define BS 2
#define NPTS 1024
#define H 8
#define DH 64
#define KNB 16
#define EMB 512
#define INNER 512
#define AINNER 256
#define POSH 64

// ---------------- scratch (static device globals; no allocation) ----------------
__device__ float g_qh[BS * H * NPTS * DH];
__device__ float g_kh[BS * H * NPTS * DH];
__device__ float g_vh[BS * H * NPTS * DH];
__device__ int   g_nbr[BS * NPTS * KNB];
__device__ float g_h1[BS * NPTS * KNB * POSH];      // rpe hidden (8 MB)
__device__ float g_rpe[BS * NPTS * KNB * INNER];
__device__ float g_attn[BS * H * NPTS * KNB * DH];
__device__ float g_norm[BS * H * KNB * DH];
__device__ float g_agg[BS * NPTS * INNER];

// ---------------- shared helpers ----------------
__device__ __forceinline__ uint32_t smem_u32(const void* p) {
    uint32_t a;
    asm("{ .reg .u64 tmp; cvta.to.shared.u64 tmp, %1; cvt.u32.u64 %0, tmp; }"
        : "=r"(a) : "l"(p));
    return a;
}

__device__ __forceinline__ void ldsm4p(uint32_t* r, uint32_t addr) {
    asm volatile("ldmatrix.sync.aligned.m8n8.x4.shared.b16 {%0,%1,%2,%3}, [%4];"
                 : "=r"(r[0]), "=r"(r[1]), "=r"(r[2]), "=r"(r[3])
                 : "r"(addr));
}

__device__ __forceinline__ void ldsm4t(uint32_t* r, uint32_t addr) {
    asm volatile("ldmatrix.sync.aligned.m8n8.x4.trans.shared.b16 {%0,%1,%2,%3}, [%4];"
                 : "=r"(r[0]), "=r"(r[1]), "=r"(r[2]), "=r"(r[3])
                 : "r"(addr));
}

__device__ __forceinline__ void mmabf(float* c, const uint32_t* a, uint32_t b0, uint32_t b1) {
    asm volatile("mma.sync.aligned.m16n8k16.row.col.f32.bf16.bf16.f32 "
                 "{%0,%1,%2,%3}, {%4,%5,%6,%7}, {%8,%9}, {%0,%1,%2,%3};"
                 : "+f"(c[0]), "+f"(c[1]), "+f"(c[2]), "+f"(c[3])
                 : "r"(a[0]), "r"(a[1]), "r"(a[2]), "r"(a[3]), "r"(b0), "r"(b1));
}

// split two floats into packed bf16 hi pair + lo (residual) pair
__device__ __forceinline__ void split_pair(float v0, float v1, uint32_t* hi, uint32_t* lo) {
    __nv_bfloat162 hv = __floats2bfloat162_rn(v0, v1);
    float f0 = __low2float(hv);
    float f1 = __high2float(hv);
    __nv_bfloat162 lv = __floats2bfloat162_rn(v0 - f0, v1 - f1);
    uint32_t uh, ul;
    memcpy(&uh, &hv, 4);
    memcpy(&ul, &lv, 4);
    *hi = uh;
    *lo = ul;
}

// ---------------- tensor-core GEMM (bf16x3): C[M,512] = A[M,K] @ B[K,512] ----------------
// MODE 0: z selects {A,B,C} triple; store permuted (b,h,i,d); no bias.
// MODE 1: C[row*512+col] = acc + bias[col].
// Tiles: BM=64, BN=64, BK=32; 256 threads; warp grid 4(m) x 2(n).
template <int MODE, int KDIM, int LDA>
__global__ void __launch_bounds__(256)
gemm_tc(const float* __restrict__ A0, const float* __restrict__ B0,
        const float* __restrict__ A1, const float* __restrict__ B1,
        const float* __restrict__ A2, const float* __restrict__ B2,
        const float* __restrict__ bias,
        float* __restrict__ C0, float* __restrict__ C1, float* __restrict__ C2) {
    const float* A = A0;
    const float* B = B0;
    float* C = C0;
    if (MODE == 0) {
        if (blockIdx.z == 1) { A = A1; B = B1; C = C1; }
        else if (blockIdx.z == 2) { A = A2; B = B2; C = C2; }
    }

    __shared__ __nv_bfloat16 Ah[64 * 40];
    __shared__ __nv_bfloat16 Al[64 * 40];
    __shared__ __nv_bfloat16 Bh[32 * 72];
    __shared__ __nv_bfloat16 Bl[32 * 72];

    int t = threadIdx.x;
    int w = t >> 5;
    int lane = t & 31;
    int wm = w & 3;
    int wn = w >> 2;
    int m0 = blockIdx.y * 64;
    int n0 = blockIdx.x * 64;

    uint32_t ah_b = smem_u32(Ah);
    uint32_t al_b = smem_u32(Al);
    uint32_t bh_b = smem_u32(Bh);
    uint32_t bl_b = smem_u32(Bl);

    float acc[4][4];
#pragma unroll
    for (int nt = 0; nt < 4; nt++) {
#pragma unroll
        for (int q = 0; q < 4; q++) acc[nt][q] = 0.f;
    }

    // ldmatrix element offsets (fixed per thread)
    int rr = lane & 7;
    int g = lane >> 3;
    int a_row = wm * 16 + rr + (g & 1) * 8;
    int a_colg = (g >> 1) * 8;
    int b_krow = lane & 15;
    int b_ng = (lane >> 4) * 8;

    for (int k0 = 0; k0 < KDIM; k0 += 32) {
        // load + split A tile (64 x 32)
#pragma unroll
        for (int p = 0; p < 2; p++) {
            int idx = t + p * 256;
            int m = idx >> 3;
            int c4 = (idx & 7) * 4;
            float4 v = *(const float4*)&A[(size_t)(m0 + m) * LDA + k0 + c4];
            uint32_t h01, l01, h23, l23;
            split_pair(v.x, v.y, &h01, &l01);
            split_pair(v.z, v.w, &h23, &l23);
            int eo = m * 40 + c4;
            *(uint32_t*)&Ah[eo] = h01;
            *(uint32_t*)&Ah[eo + 2] = h23;
            *(uint32_t*)&Al[eo] = l01;
            *(uint32_t*)&Al[eo + 2] = l23;
        }
        // load + split B tile (32 x 64), keep [k][n] layout
#pragma unroll
        for (int p = 0; p < 2; p++) {
            int idx = t + p * 256;
            int k = idx >> 4;
            int n4 = (idx & 15) * 4;
            float4 v = *(const float4*)&B[(size_t)(k0 + k) * 512 + n0 + n4];
            uint32_t h01, l01, h23, l23;
            split_pair(v.x, v.y, &h01, &l01);
            split_pair(v.z, v.w, &h23, &l23);
            int eo = k * 72 + n4;
            *(uint32_t*)&Bh[eo] = h01;
            *(uint32_t*)&Bh[eo + 2] = h23;
            *(uint32_t*)&Bl[eo] = l01;
            *(uint32_t*)&Bl[eo + 2] = l23;
        }
        __syncthreads();

#pragma unroll
        for (int ks = 0; ks < 32; ks += 16) {
            uint32_t ahi[4];
            uint32_t alo[4];
            uint32_t aoff = (uint32_t)((a_row * 40 + ks + a_colg) * 2);
            ldsm4p(ahi, ah_b + aoff);
            ldsm4p(alo, al_b + aoff);
#pragma unroll
            for (int nh = 0; nh < 2; nh++) {
                uint32_t bhv[4];
                uint32_t blv[4];
                uint32_t boff = (uint32_t)(((ks + b_krow) * 72 + wn * 32 + nh * 16 + b_ng) * 2);
                ldsm4t(bhv, bh_b + boff);
                ldsm4t(blv, bl_b + boff);
                mmabf(acc[nh * 2], ahi, bhv[0], bhv[1]);
                mmabf(acc[nh * 2], ahi, blv[0], blv[1]);
                mmabf(acc[nh * 2], alo, bhv[0], bhv[1]);
                mmabf(acc[nh * 2 + 1], ahi, bhv[2], bhv[3]);
                mmabf(acc[nh * 2 + 1], ahi, blv[2], blv[3]);
                mmabf(acc[nh * 2 + 1], alo, bhv[2], bhv[3]);
            }
        }
        __syncthreads();
    }

    // epilogue: acc[nt] holds rows (r, r+8), cols nt*8 + 2cq (+1)
    int r = lane >> 2;
    int cq = lane & 3;
#pragma unroll
    for (int nt = 0; nt < 4; nt++) {
        int col = n0 + wn * 32 + nt * 8 + 2 * cq;
        int row0 = m0 + wm * 16 + r;
        int row1 = row0 + 8;
        if (MODE == 0) {
            int hh = (col >> 6) & 7;
            int dd = col & 63;
            int b0i = row0 >> 10, i0 = row0 & 1023;
            int b1i = row1 >> 10, i1 = row1 & 1023;
            *(float2*)&C[(((size_t)(b0i * H + hh) * NPTS) + i0) * DH + dd] =
                make_float2(acc[nt][0], acc[nt][1]);
            *(float2*)&C[(((size_t)(b1i * H + hh) * NPTS) + i1) * DH + dd] =
                make_float2(acc[nt][2], acc[nt][3]);
        } else {
            float bz0 = bias[col];
            float bz1 = bias[col + 1];
            *(float2*)&C[(size_t)row0 * 512 + col] = make_float2(acc[nt][0] + bz0, acc[nt][1] + bz1);
            *(float2*)&C[(size_t)row1 * 512 + col] = make_float2(acc[nt][2] + bz0, acc[nt][3] + bz1);
        }
    }
}

// ---------------- KNN: warp-per-query, exact stable (d2, idx) selection ----------------
__global__ void knn_kernel(const float* __restrict__ canonical) {
    __shared__ float sx[NPTS], sy[NPTS], sz[NPTS];
    int b = blockIdx.x >> 7;
    int t = threadIdx.x;
    int wid = t >> 5, lane = t & 31;
    for (int p = t; p < NPTS; p += 256) {
        sx[p] = canonical[(b * NPTS + p) * 3 + 0];
        sy[p] = canonical[(b * NPTS + p) * 3 + 1];
        sz[p] = canonical[(b * NPTS + p) * 3 + 2];
    }
    __syncthreads();
    int i = (blockIdx.x & 127) * 8 + wid;
    float qx = sx[i], qy = sy[i], qz = sz[i];
    float prev_d = -1.f;
    int prev_j = -1;
    for (int s = 0; s < KNB; s++) {
        float bd = INFINITY;
        int bj = 1 << 30;
        for (int p = lane; p < NPTS; p += 32) {
            float dx = sx[p] - qx, dy = sy[p] - qy, dz = sz[p] - qz;
            float d2 = dx * dx + dy * dy + dz * dz;
            bool gt_prev = (d2 > prev_d) || (d2 == prev_d && p > prev_j);
            bool lt_best = (d2 < bd) || (d2 == bd && p < bj);
            if (gt_prev && lt_best) { bd = d2; bj = p; }
        }
#pragma unroll
        for (int off = 16; off; off >>= 1) {
            float od = __shfl_down_sync(0xFFFFFFFFu, bd, off);
            int   oj = __shfl_down_sync(0xFFFFFFFFu, bj, off);
            if (od < bd || (od == bd && oj < bj)) { bd = od; bj = oj; }
        }
        bd = __shfl_sync(0xFFFFFFFFu, bd, 0);
        bj = __shfl_sync(0xFFFFFFFFu, bj, 0);
        if (lane == 0) g_nbr[(b * NPTS + i) * KNB + s] = bj;
        prev_d = bd;
        prev_j = bj;
    }
}

// ---------------- RPE hidden layer: h1[bij][64] = relu(rel @ pw1 + pb1) ----------------
__global__ void __launch_bounds__(256)
h1_kernel(const float* __restrict__ canonical,
          const float* __restrict__ pw1, const float* __restrict__ pb1) {
    int bi = blockIdx.x;
    int b = bi >> 10;
    int t = threadIdx.x;
    __shared__ float relS[KNB][3];

    if (t < KNB) {
        int nv = g_nbr[bi * KNB + t];
#pragma unroll
        for (int c = 0; c < 3; c++) {
            relS[t][c] = canonical[(b * NPTS + nv) * 3 + c] - canonical[bi * 3 + c];
        }
    }
    __syncthreads();

    int e = t & 63;
    int j0 = (t >> 6) * 4;
    float w0 = pw1[e], w1 = pw1[64 + e], w2 = pw1[128 + e], bb = pb1[e];
#pragma unroll
    for (int jj = 0; jj < 4; jj++) {
        int j = j0 + jj;
        float a = relS[j][0] * w0 + relS[j][1] * w1 + relS[j][2] * w2 + bb;
        g_h1[(size_t)(bi * KNB + j) * POSH + e] = fmaxf(a, 0.f);
    }
}

// faithful replication of the reference's flattened-view gather
__device__ __forceinline__ int gather_row(int b, int h, int i, int j) {
    int m = 2 * i + (j >> 3);
    int ip = h * 128 + (m >> 4);
    int jp = m & 15;
    int nv = g_nbr[(b * NPTS + ip) * KNB + jp];
    int cc = nv * 8 + (j & 7);
    int h2 = cc >> 10;
    int i2 = cc & 1023;
    return ((b * H + h2) * NPTS + i2) * DH;
}

// smem layout (bytes) for attn
#define AT_W1H 0
#define AT_W1L 36864
#define AT_W2H 73728
#define AT_W2L 107520
#define AT_X   141312
#define AT_AB1 178176
#define AT_AB2 179200
#define AT_SMEM 179456

// warp-per-i tensor-core attn MLP (bf16x3) + softmax. 32 i per block, h uniform.
__global__ void __launch_bounds__(256, 1)
attn_tc_kernel(const float* __restrict__ aw1, const float* __restrict__ ab1,
               const float* __restrict__ aw2, const float* __restrict__ ab2) {
    extern __shared__ char smem[];
    uint32_t sb = smem_u32(smem);
    int t = threadIdx.x;
    int w = t >> 5;
    int lane = t & 31;
    int h = ((blockIdx.x * 32) >> 10) & 7;

    __nv_bfloat16* W1H = (__nv_bfloat16*)(smem + AT_W1H);   // [256][72]
    __nv_bfloat16* W1L = (__nv_bfloat16*)(smem + AT_W1L);
    __nv_bfloat16* W2H = (__nv_bfloat16*)(smem + AT_W2H);   // [64][264]
    __nv_bfloat16* W2L = (__nv_bfloat16*)(smem + AT_W2L);
    float* sab1 = (float*)(smem + AT_AB1);
    float* sab2 = (float*)(smem + AT_AB2);

    for (int idx = t; idx < 256 * 64; idx += 256) {
        int e = idx >> 6;
        int d = idx & 63;
        float v = aw1[(h * AINNER + e) * DH + d];
        __nv_bfloat16 hi = __float2bfloat16_rn(v);
        W1H[e * 72 + d] = hi;
        W1L[e * 72 + d] = __float2bfloat16_rn(v - __bfloat162float(hi));
    }
    for (int idx = t; idx < 64 * 256; idx += 256) {
        int d = idx >> 8;
        int e = idx & 255;
        float v = aw2[(h * DH + d) * AINNER + e];
        __nv_bfloat16 hi = __float2bfloat16_rn(v);
        W2H[d * 264 + e] = hi;
        W2L[d * 264 + e] = __float2bfloat16_rn(v - __bfloat162float(hi));
    }
    sab1[t] = ab1[h * AINNER + t];
    if (t < 64) sab2[t] = ab2[h * DH + t];
    __syncthreads();

    int r  = lane >> 2;
    int cq = lane & 3;
    int rr = lane & 7;
    int g  = lane >> 3;
    uint32_t xh_base = sb + AT_X + w * 4608;
    uint32_t xl_base = xh_base + 2304;
    char* xh_ptr = smem + AT_X + w * 4608;
    char* xl_ptr = xh_ptr + 2304;
    uint32_t w1h_base = sb + AT_W1H;
    uint32_t w1l_base = sb + AT_W1L;
    uint32_t w2h_base = sb + AT_W2H;
    uint32_t w2l_base = sb + AT_W2L;

    for (int l = 0; l < 4; l++) {
        int bhi = blockIdx.x * 32 + w * 4 + l;
        int i = bhi & 1023;
        int b = bhi >> 13;

        int sr = 0;
        if (lane < 16) sr = gather_row(b, h, i, lane);

#pragma unroll
        for (int it = 0; it < 8; it++) {
            int idx = lane + it * 32;
            int j  = idx >> 4;
            int d4 = idx & 15;
            int ro = __shfl_sync(0xFFFFFFFFu, sr, j) + d4 * 4;
            float4 qv = *(const float4*)&g_qh[ro];
            float4 kv = *(const float4*)&g_kh[ro];
            float4 rv = *(const float4*)&g_rpe[((size_t)(b * NPTS + i) * KNB + j) * INNER + h * DH + d4 * 4];
            uint32_t h01, l01, h23, l23;
            split_pair(qv.x - kv.x + rv.x, qv.y - kv.y + rv.y, &h01, &l01);
            split_pair(qv.z - kv.z + rv.z, qv.w - kv.w + rv.w, &h23, &l23);
            int off = j * 144 + d4 * 8;
            *(uint32_t*)(xh_ptr + off)     = h01;
            *(uint32_t*)(xh_ptr + off + 4) = h23;
            *(uint32_t*)(xl_ptr + off)     = l01;
            *(uint32_t*)(xl_ptr + off + 4) = l23;
        }
        __syncwarp();

        float acc2[8][4];
#pragma unroll
        for (int nt2 = 0; nt2 < 8; nt2++) {
            int d0 = nt2 * 8 + 2 * cq;
            acc2[nt2][0] = sab2[d0];
            acc2[nt2][1] = sab2[d0 + 1];
            acc2[nt2][2] = acc2[nt2][0];
            acc2[nt2][3] = acc2[nt2][1];
        }

#pragma unroll
        for (int half = 0; half < 2; half++) {
            float acc1[16][4];
#pragma unroll
            for (int nt = 0; nt < 16; nt++) {
                int e0 = (half * 16 + nt) * 8 + 2 * cq;
                acc1[nt][0] = sab1[e0];
                acc1[nt][1] = sab1[e0 + 1];
                acc1[nt][2] = acc1[nt][0];
                acc1[nt][3] = acc1[nt][1];
            }
#pragma unroll
            for (int kt = 0; kt < 4; kt++) {
                uint32_t ahi[4];
                uint32_t alo[4];
                uint32_t aoff = (uint32_t)((rr + (g & 1) * 8) * 144 + (kt * 16 + (g >> 1) * 8) * 2);
                ldsm4p(ahi, xh_base + aoff);
                ldsm4p(alo, xl_base + aoff);
#pragma unroll
                for (int ntp = 0; ntp < 8; ntp++) {
                    int erow = (half * 16 + 2 * ntp + (g >> 1)) * 8 + rr;
                    int dcol = kt * 16 + (g & 1) * 8;
                    uint32_t boff = (uint32_t)(erow * 144 + dcol * 2);
                    uint32_t bhv[4];
                    uint32_t blv[4];
                    ldsm4p(bhv, w1h_base + boff);
                    ldsm4p(blv, w1l_base + boff);
                    mmabf(acc1[2 * ntp], ahi, bhv[0], bhv[1]);
                    mmabf(acc1[2 * ntp], ahi, blv[0], blv[1]);
                    mmabf(acc1[2 * ntp], alo, bhv[0], bhv[1]);
                    mmabf(acc1[2 * ntp + 1], ahi, bhv[2], bhv[3]);
                    mmabf(acc1[2 * ntp + 1], ahi, blv[2], blv[3]);
                    mmabf(acc1[2 * ntp + 1], alo, bhv[2], bhv[3]);
                }
            }
#pragma unroll
            for (int ap = 0; ap < 8; ap++) {
                float v0 = fmaxf(acc1[2 * ap][0], 0.f);
                float v1 = fmaxf(acc1[2 * ap][1], 0.f);
                float v2 = fmaxf(acc1[2 * ap][2], 0.f);
                float v3 = fmaxf(acc1[2 * ap][3], 0.f);
                float v4 = fmaxf(acc1[2 * ap + 1][0], 0.f);
                float v5 = fmaxf(acc1[2 * ap + 1][1], 0.f);
                float v6 = fmaxf(acc1[2 * ap + 1][2], 0.f);
                float v7 = fmaxf(acc1[2 * ap + 1][3], 0.f);
                uint32_t a2h[4];
                uint32_t a2l[4];
                split_pair(v0, v1, &a2h[0], &a2l[0]);
                split_pair(v2, v3, &a2h[1], &a2l[1]);
                split_pair(v4, v5, &a2h[2], &a2l[2]);
                split_pair(v6, v7, &a2h[3], &a2l[3]);
                int kcol = (half * 8 + ap) * 16;
#pragma unroll
                for (int np = 0; np < 4; np++) {
                    int drow = (2 * np + (g >> 1)) * 8 + rr;
                    int ecol = kcol + (g & 1) * 8;
                    uint32_t b2off = (uint32_t)(drow * 528 + ecol * 2);
                    uint32_t b2h[4];
                    uint32_t b2l[4];
                    ldsm4p(b2h, w2h_base + b2off);
                    ldsm4p(b2l, w2l_base + b2off);
                    mmabf(acc2[2 * np], a2h, b2h[0], b2h[1]);
                    mmabf(acc2[2 * np], a2h, b2l[0], b2l[1]);
                    mmabf(acc2[2 * np], a2l, b2h[0], b2h[1]);
                    mmabf(acc2[2 * np + 1], a2h, b2h[2], b2h[3]);
                    mmabf(acc2[2 * np + 1], a2h, b2l[2], b2l[3]);
                    mmabf(acc2[2 * np + 1], a2l, b2h[2], b2h[3]);
                }
            }
        }

        size_t base = (size_t)bhi * KNB * DH;
#pragma unroll
        for (int nt2 = 0; nt2 < 8; nt2++) {
            float c0 = acc2[nt2][0];
            float c1 = acc2[nt2][1];
            float c2 = acc2[nt2][2];
            float c3 = acc2[nt2][3];
            float ma = fmaxf(c0, c2);
            float mb = fmaxf(c1, c3);
#pragma unroll
            for (int mk = 4; mk <= 16; mk <<= 1) {
                ma = fmaxf(ma, __shfl_xor_sync(0xFFFFFFFFu, ma, mk));
                mb = fmaxf(mb, __shfl_xor_sync(0xFFFFFFFFu, mb, mk));
            }
            float e0 = expf(c0 - ma);
            float e2 = expf(c2 - ma);
            float e1 = expf(c1 - mb);
            float e3 = expf(c3 - mb);
            float sa = e0 + e2;
            float sc = e1 + e3;
#pragma unroll
            for (int mk = 4; mk <= 16; mk <<= 1) {
                sa += __shfl_xor_sync(0xFFFFFFFFu, sa, mk);
                sc += __shfl_xor_sync(0xFFFFFFFFu, sc, mk);
            }
            float ia = 1.f / sa;
            float ic = 1.f / sc;
            int d0 = nt2 * 8 + 2 * cq;
            *(float2*)&g_attn[base + (size_t)r * DH + d0] = make_float2(e0 * ia, e1 * ic);
            *(float2*)&g_attn[base + (size_t)(r + 8) * DH + d0] = make_float2(e2 * ia, e3 * ic);
        }
        __syncwarp();
    }
}

// ---------------- norm over i: norm[b,h,j,d] = sqrt(sum_i attn^2) ----------------
__global__ void norm_kernel() {
    int bhj = blockIdx.x;
    int j = bhj & 15;
    int bh = bhj >> 4;
    int t = threadIdx.x;
    int d = t & 63;
    int iq = t >> 6;
    size_t base = (size_t)bh * NPTS * KNB * DH + j * DH + d;
    float s = 0.f;
#pragma unroll 4
    for (int i = iq * 256; i < iq * 256 + 256; i++) {
        float v = g_attn[base + (size_t)i * KNB * DH];
        s += v * v;
    }
    __shared__ float rshared[4][64];
    rshared[iq][d] = s;
    __syncthreads();
    if (t < 64) g_norm[bhj * DH + t] = sqrtf(rshared[0][t] + rshared[1][t] + rshared[2][t] + rshared[3][t]);
}

// ---------------- aggregate ----------------
__global__ void agg_kernel() {
    int t = threadIdx.x;
    int ii = t >> 6;
    int d = t & 63;
    int bhi = blockIdx.x * 4 + ii;
    int i = bhi & 1023;
    int h = (bhi >> 10) & 7;
    int b = bhi >> 13;

    __shared__ int srow[4][KNB];
    if (t < 64) {
        int i2 = t >> 4;
        int j = t & 15;
        srow[i2][j] = gather_row(b, h, (blockIdx.x * 4 + i2) & 1023, j);
    }
    __syncthreads();

    int bh = b * H + h;
    size_t abase = (size_t)bhi * KNB * DH + d;
    float acc = 0.f;
#pragma unroll
    for (int j = 0; j < KNB; j++) {
        float a = g_attn[abase + j * DH];
        float nm = g_norm[(bh * KNB + j) * DH + d];
        a /= fmaxf(nm, 1e-12f);
        float vg = g_vh[srow[ii][j] + d] +
                   g_rpe[(size_t)((b * NPTS + i) * KNB + j) * INNER + h * DH + d];
        acc = fmaf(a, vg, acc);
    }
    g_agg[(b * NPTS + i) * INNER + h * DH + d] = acc;
}

// ---------------- launch ----------------
extern "C" void kernel_launch(void* const* d_in, const int* in_sizes, int n_in,
                              void* d_out, int out_size) {
    const float* query     = (const float*)d_in[0];
    const float* key_in    = (const float*)d_in[1];
    const float* value     = (const float*)d_in[2];
    const float* canonical = (const float*)d_in[3];
    const float* w_q       = (const float*)d_in[4];
    const float* w_k       = (const float*)d_in[5];
    const float* w_v       = (const float*)d_in[6];
    const float* w_out     = (const float*)d_in[7];
    const float* b_out     = (const float*)d_in[8];
    const float* pos_w1    = (const float*)d_in[9];
    const float* pos_b1    = (const float*)d_in[10];
    const float* pos_w2    = (const float*)d_in[11];
    const float* pos_b2    = (const float*)d_in[12];
    const float* aw1       = (const float*)d_in[13];
    const float* ab1       = (const float*)d_in[14];
    const float* aw2       = (const float*)d_in[15];
    const float* ab2       = (const float*)d_in[16];
    float* out = (float*)d_out;

    float* qh;  cudaGetSymbolAddress((void**)&qh,  g_qh);
    float* kh;  cudaGetSymbolAddress((void**)&kh,  g_kh);
    float* vh;  cudaGetSymbolAddress((void**)&vh,  g_vh);
    float* h1;  cudaGetSymbolAddress((void**)&h1,  g_h1);
    float* rpe; cudaGetSymbolAddress((void**)&rpe, g_rpe);
    float* agg; cudaGetSymbolAddress((void**)&agg, g_agg);

    cudaFuncSetAttribute(attn_tc_kernel,
                         cudaFuncAttributeMaxDynamicSharedMemorySize, AT_SMEM);

    // projections (tensor-core, permuted store)
    dim3 pgrid(8, 32, 3);
    gemm_tc<0, 512, 512><<<pgrid, 256>>>(query, w_q, key_in, w_k, value, w_v,
                                         nullptr, qh, kh, vh);

    knn_kernel<<<256, 256>>>(canonical);
    h1_kernel<<<BS * NPTS, 256>>>(canonical, pos_w1, pos_b1);

    // rpe second layer: [32768 x 64] @ [64 x 512] + pb2 (tensor-core)
    dim3 rgrid(8, 512, 1);
    gemm_tc<1, 64, 64><<<rgrid, 256>>>(h1, pos_w2, nullptr, nullptr, nullptr, nullptr,
                                       pos_b2, rpe, nullptr, nullptr);

    attn_tc_kernel<<<BS * H * NPTS / 32, 256, AT_SMEM>>>(aw1, ab1, aw2, ab2);
    norm_kernel<<<BS * H * KNB, 256>>>();
    agg_kernel<<<BS * H * NPTS / 4, 256>>>();

    // output projection (tensor-core, bias)
    dim3 ogrid(8, 32, 1);
    gemm_tc<1, 512, 512><<<ogrid, 256>>>(agg, w_out, nullptr, nullptr, nullptr, nullptr,
                                         b_out, out, nullptr, nullptr);
}